// round 8
// baseline (speedup 1.0000x reference)
#include <cuda_runtime.h>

// Problem constants
#define Bq      128
#define Tq      1024
#define IN_DIM  17
#define Hq      512
#define OUT_DIM 17

// Work partition: layer0 blocks own NU0 hidden units (K=512+17),
// layer1 blocks own NU1 units (K=1024). Balanced: 3.25M vs 3.15M MACs/block.
#define NU0  12
#define NU1  6
#define NB0  43            // ceil(512/12)
#define NB1  86            // ceil(512/6)
#define NBLK (NB0 + NB1)   // 129 blocks <= 148 SMs -> all co-resident

#define KC   64            // K-chunk staged in smem
#define THREADS 256

// Dynamic smem: Hs[KC][128] floats + Ws2[KC][G+1] u64 (G<=48)
#define SMEM_BYTES (KC*Bq*4 + KC*(4*NU0 + 1)*8)   // 32768 + 25088 = 57856

// Persistent state (device globals: allocation-free scratch).
// h layout: [unit][batch] -> h[k*128 + b]; ping-pong on step parity.
__device__ float g_h0[2][Hq * Bq];
__device__ float g_h1[2][Hq * Bq];
__device__ float g_c0[Hq * Bq];
__device__ float g_c1[Hq * Bq];
__device__ float g_xT[Tq][IN_DIM][Bq];   // transposed input, [t][i][b]

// Grid barrier state (sense-reversal; self-consistent across graph replays:
// count returns to 0 after every barrier, gen only needs to *change*).
__device__ unsigned g_bar_count = 0;
__device__ volatile unsigned g_bar_gen = 0;

typedef unsigned long long u64;

__device__ __forceinline__ void grid_barrier() {
    __syncthreads();
    if (threadIdx.x == 0) {
        unsigned gen = g_bar_gen;          // read BEFORE arriving
        __threadfence();                   // make this block's writes visible
        if (atomicAdd(&g_bar_count, 1) == NBLK - 1) {
            g_bar_count = 0;
            __threadfence();
            g_bar_gen = gen + 1;           // release (volatile -> L2)
        } else {
            while (g_bar_gen == gen) __nanosleep(64);
        }
    }
    __syncthreads();
}

// Packed f32x2 FMA: 2 fp32 FMAs per issue slot.
__device__ __forceinline__ void fma2(u64 &a, u64 x, u64 y) {
    asm("fma.rn.f32x2 %0, %1, %2, %0;" : "+l"(a) : "l"(x), "l"(y));
}
__device__ __forceinline__ u64 pack2(float w) {
    u64 r; asm("mov.b64 %0, {%1, %1};" : "=l"(r) : "f"(w)); return r;
}

// C[128 x G] += Hsrc[128 x 512] @ W_slice[G x 512]^T,  G = 4*NU.
// Hsrc layout [k*128+b] (read via ld.cg: cross-SM producer).
// Threads: 32 row-threads (4 batch rows each = 2 f32x2) x 8 col-threads (CT cols).
template<int NU>
__device__ __forceinline__ void gemm512(const float* __restrict__ Hsrc,
                                        const float* __restrict__ W,
                                        int u0, u64 (&acc)[2][NU/2], float* smem)
{
    constexpr int G = 4 * NU, CT = NU / 2, WS = G + 1;
    const int tid = threadIdx.x;
    const int rt = tid & 31, ct = tid >> 5;
    float* Hs = smem;                       // [KC][128] floats
    u64*   Ws2 = (u64*)(smem + KC * Bq);    // [KC][WS] duplicated weights

    for (int k0 = 0; k0 < Hq; k0 += KC) {
        __syncthreads();
        {   // stage H chunk: 2048 float4, 8 per thread, coalesced, L2 path
            const float4* s4 = (const float4*)(Hsrc + k0 * Bq);
            float4* d4 = (float4*)Hs;
            #pragma unroll
            for (int j = 0; j < (KC * Bq / 4) / THREADS; ++j)
                d4[tid + j * THREADS] = __ldcg(s4 + tid + j * THREADS);
        }
        // stage W chunk duplicated: Ws2[k][c] = {w,w}, w = W[row(c)*512 + k0+k]
        #pragma unroll
        for (int j = 0; j < (KC * G) / THREADS; ++j) {
            int idx = tid + j * THREADS;
            int c = idx >> 6, k = idx & (KC - 1);     // KC == 64
            int unit = u0 + (c % NU); if (unit > Hq - 1) unit = Hq - 1; // pad clamp
            int row = (c / NU) * Hq + unit;
            Ws2[k * WS + c] = pack2(__ldg(&W[row * Hq + k0 + k]));
        }
        __syncthreads();

        #pragma unroll 8
        for (int k = 0; k < KC; ++k) {
            ulonglong2 h = *(const ulonglong2*)(Hs + k * Bq + rt * 4); // LDS.128
            const u64* wr = Ws2 + k * WS + ct * CT;
            #pragma unroll
            for (int cc = 0; cc < CT; ++cc) {
                u64 w2 = wr[cc];                       // broadcast LDS.64
                fma2(acc[0][cc], h.x, w2);
                fma2(acc[1][cc], h.y, w2);
            }
        }
    }
}

// Layer-0 input contribution: acc += x_t[128 x 17] @ wih0_slice[G x 17]^T
__device__ __forceinline__ void xcontrib(int u0, int t,
                                         const float* __restrict__ wih0,
                                         u64 (&acc)[2][NU0/2], float* smem)
{
    constexpr int NU = NU0, CT = NU / 2;
    const int tid = threadIdx.x;
    const int rt = tid & 31, ct = tid >> 5;
    float* xs = smem;  // [17][128]
    __syncthreads();
    {   // coalesced stage of the transposed x_t slice (2176 floats)
        const float* src = &g_xT[t][0][0];
        for (int idx = tid; idx < IN_DIM * Bq; idx += THREADS)
            xs[idx] = __ldcg(src + idx);
    }
    __syncthreads();

    int rowc[CT];
    #pragma unroll
    for (int cc = 0; cc < CT; ++cc) {
        int c = ct * CT + cc;
        int unit = u0 + (c % NU); if (unit > Hq - 1) unit = Hq - 1;
        rowc[cc] = (c / NU) * Hq + unit;
    }
    #pragma unroll
    for (int i = 0; i < IN_DIM; ++i) {
        ulonglong2 h = *(const ulonglong2*)(xs + i * Bq + rt * 4);
        #pragma unroll
        for (int cc = 0; cc < CT; ++cc) {
            u64 w2 = pack2(__ldg(&wih0[rowc[cc] * IN_DIM + i]));  // tiny, L1-hot
            fma2(acc[0][cc], h.x, w2);
            fma2(acc[1][cc], h.y, w2);
        }
    }
}

// Gates -> (c,h): exchange acc through smem so each thread owns one batch row
// across all 4 gates of its units. c updated in place (exclusive block ownership,
// block never migrates -> L1-coherent). h written via st.cg for cross-SM readers.
template<int NU>
__device__ __forceinline__ void epilogue(int u0, u64 (&acc)[2][NU/2],
                                         const float* __restrict__ bih,
                                         const float* __restrict__ bhh,
                                         float* __restrict__ cbuf,
                                         float* __restrict__ hdst, float* smem)
{
    constexpr int CT = NU / 2;
    const int tid = threadIdx.x;
    const int rt = tid & 31, ct = tid >> 5;
    __syncthreads();
    ulonglong2* Gs = (ulonglong2*)smem;     // float layout [c*128 + b]
    #pragma unroll
    for (int cc = 0; cc < CT; ++cc) {
        int c = ct * CT + cc;
        Gs[c * 32 + rt] = make_ulonglong2(acc[0][cc], acc[1][cc]);  // STS.128
    }
    __syncthreads();
    const float* Gf = smem;
    const int b = tid & 127;
    const int g0 = (tid >> 7) * (NU / 2);   // split units across thread halves
    #pragma unroll
    for (int u = g0; u < g0 + NU / 2; ++u) {
        int unit = u0 + u;
        if (unit >= Hq) break;
        float gi = Gf[(u         ) * Bq + b] + bih[unit         ] + bhh[unit         ];
        float gf = Gf[(u +     NU) * Bq + b] + bih[unit +     Hq] + bhh[unit +     Hq];
        float gg = Gf[(u + 2 * NU) * Bq + b] + bih[unit + 2 * Hq] + bhh[unit + 2 * Hq];
        float go = Gf[(u + 3 * NU) * Bq + b] + bih[unit + 3 * Hq] + bhh[unit + 3 * Hq];
        float ig = 1.f / (1.f + __expf(-gi));
        float fg = 1.f / (1.f + __expf(-gf));
        float og = 1.f / (1.f + __expf(-go));
        float gv = tanhf(gg);
        int off = unit * Bq + b;
        float cn = fg * cbuf[off] + ig * gv;
        cbuf[off] = cn;
        __stcg(&hdst[off], og * tanhf(cn));
    }
}

// Single persistent kernel: init state, 1025 pipelined steps with grid
// barriers, final linear. Blocks [0,NB0): layer0 step t. [NB0,NBLK): layer1
// step t-1. One grid barrier per step.
__global__ void __launch_bounds__(THREADS, 1)
lstm_persistent(const float* __restrict__ x,
                const float* __restrict__ wih0, const float* __restrict__ whh0,
                const float* __restrict__ bih0, const float* __restrict__ bhh0,
                const float* __restrict__ wih1, const float* __restrict__ whh1,
                const float* __restrict__ bih1, const float* __restrict__ bhh1,
                const float* __restrict__ lin_w, const float* __restrict__ lin_b,
                float* __restrict__ out)
{
    extern __shared__ float smem[];
    const int blk = blockIdx.x;
    const int tid = threadIdx.x;

    // ---- init: zero state, transpose x into [t][i][b] ----
    {
        const int gi = blk * THREADS + tid, gs = NBLK * THREADS;
        for (int i = gi; i < 2 * Hq * Bq; i += gs) {
            ((float*)g_h0)[i] = 0.f;
            ((float*)g_h1)[i] = 0.f;
        }
        for (int i = gi; i < Hq * Bq; i += gs) {
            g_c0[i] = 0.f;
            g_c1[i] = 0.f;
        }
        const int NX = Bq * Tq * IN_DIM;
        for (int i = gi; i < NX; i += gs) {
            int b = i / (Tq * IN_DIM);
            int r = i - b * (Tq * IN_DIM);
            int t = r / IN_DIM;
            int ii = r - t * IN_DIM;
            g_xT[t][ii][b] = x[i];
        }
    }
    grid_barrier();

    if (blk < NB0) {
        const int u0 = blk * NU0;
        #pragma unroll 1
        for (int t = 0; t <= Tq; ++t) {
            if (t < Tq) {
                u64 acc[2][NU0 / 2];
                #pragma unroll
                for (int r = 0; r < 2; ++r)
                    #pragma unroll
                    for (int c = 0; c < NU0 / 2; ++c) acc[r][c] = 0ull;
                gemm512<NU0>(g_h0[(t + 1) & 1], whh0, u0, acc, smem);
                xcontrib(u0, t, wih0, acc, smem);
                epilogue<NU0>(u0, acc, bih0, bhh0, g_c0, g_h0[t & 1], smem);
            }
            grid_barrier();
        }
    } else {
        const int u0 = (blk - NB0) * NU1;
        #pragma unroll 1
        for (int t = 0; t <= Tq; ++t) {
            if (t >= 1) {
                const int s = t - 1;
                u64 acc[2][NU1 / 2];
                #pragma unroll
                for (int r = 0; r < 2; ++r)
                    #pragma unroll
                    for (int c = 0; c < NU1 / 2; ++c) acc[r][c] = 0ull;
                gemm512<NU1>(g_h0[s & 1],       wih1, u0, acc, smem);  // y0_s
                gemm512<NU1>(g_h1[(s + 1) & 1], whh1, u0, acc, smem);  // h1_{s-1}
                epilogue<NU1>(u0, acc, bih1, bhh1, g_c1, g_h1[s & 1], smem);
            }
            grid_barrier();
        }
    }

    // ---- final linear: out[b][o] = h1_last[:,b] . lin_w[o,:] + lin_b[o] ----
    if (blk < OUT_DIM && tid < Bq) {
        const int o = blk, b = tid;
        const float* h = g_h1[(Tq - 1) & 1];
        float a = __ldg(&lin_b[o]);
        #pragma unroll 8
        for (int k = 0; k < Hq; ++k)
            a += __ldcg(&h[k * Bq + b]) * __ldg(&lin_w[o * Hq + k]);
        out[b * OUT_DIM + o] = a;
    }
}

extern "C" void kernel_launch(void* const* d_in, const int* in_sizes, int n_in,
                              void* d_out, int out_size)
{
    const float* x     = (const float*)d_in[0];
    const float* wih0  = (const float*)d_in[1];
    const float* whh0  = (const float*)d_in[2];
    const float* bih0  = (const float*)d_in[3];
    const float* bhh0  = (const float*)d_in[4];
    const float* wih1  = (const float*)d_in[5];
    const float* whh1  = (const float*)d_in[6];
    const float* bih1  = (const float*)d_in[7];
    const float* bhh1  = (const float*)d_in[8];
    const float* lin_w = (const float*)d_in[9];
    const float* lin_b = (const float*)d_in[10];
    float* out = (float*)d_out;

    cudaFuncSetAttribute(lstm_persistent,
                         cudaFuncAttributeMaxDynamicSharedMemorySize, SMEM_BYTES);

    lstm_persistent<<<NBLK, THREADS, SMEM_BYTES>>>(
        x, wih0, whh0, bih0, bhh0, wih1, whh1, bih1, bhh1, lin_w, lin_b, out);
}